// round 8
// baseline (speedup 1.0000x reference)
#include <cuda_runtime.h>
#include <cstdint>
#include <math.h>

#define L_LEN     100000
#define B_ROWS    512
#define HALF      50000        // pooled elements per row
#define HALF_CTA  25000        // pooled elements per cluster-rank CTA
#define NPAIRS    12500        // pooled pairs per CTA
#define QOUT4     6250         // float4-quad groups per CTA in write phase
#define NOISE_STD 0.04f
#define NTHREADS  512

// npool[j] = (noise[2j] + noise[2j+1]) * STD / 2. Row-invariant, L2-resident.
__device__ float g_npool[HALF];

__global__ void noise_pool_kernel(const float* __restrict__ noise) {
    int j = blockIdx.x * blockDim.x + threadIdx.x;
    if (j < HALF) {
        float2 n = reinterpret_cast<const float2*>(noise)[j];
        g_npool[j] = (n.x + n.y) * (0.5f * NOISE_STD);
    }
}

__device__ __forceinline__ unsigned int smem_u32(const void* p) {
    unsigned int a;
    asm("{ .reg .u64 t; cvta.to.shared.u64 t, %1; cvt.u32.u64 %0, t; }"
        : "=r"(a) : "l"(p));
    return a;
}

// One row per 2-CTA cluster; 512 threads/CTA, 2 CTAs/SM (100KB smem each).
// 64-reg budget lets the load loop keep ~4 LDG.128 in flight per thread.
__global__ __launch_bounds__(NTHREADS, 2) __cluster_dims__(2, 1, 1)
void triple_transform_kernel(const float* __restrict__ x,
                             const int* __restrict__ move_p,
                             float* __restrict__ out) {
    extern __shared__ float s_pool[];              // HALF_CTA floats (100 KB)
    __shared__ float rs[16], rq[16];
    __shared__ float s_part[2];
    __shared__ float s_mu, s_inv;

    unsigned int rank;
    asm("mov.u32 %0, %%cluster_ctarank;" : "=r"(rank));
    const int b = blockIdx.x >> 1;
    const int jbase = (int)rank * HALF_CTA;

    const float* xr = x + (size_t)b * L_LEN;

    int move = *move_p;
    move %= L_LEN; if (move < 0) move += L_LEN;

    float sum = 0.f, sumsq = 0.f;

    if ((move & 3) == 0) {
        // move % 4 == 0: each pooled pair (j0, j0+1), j0 even, reads one
        // 16B-aligned float4 of x. Wrap only possible for rank 0's head.
        const float2* xr2 = reinterpret_cast<const float2*>(xr);
        const float2* np2 = reinterpret_cast<const float2*>(g_npool) + rank * NPAIRS;
        float2* sp2 = reinterpret_cast<float2*>(s_pool);
        const int moff = move >> 1;                 // even
        const int ibase = jbase - moff;             // float2 idx of pair start

        #pragma unroll 4
        for (int t = threadIdx.x; t < NPAIRS; t += NTHREADS) {
            int i = ibase + 2 * t;                  // even -> float4 aligned
            float4 v;
            if (i >= 0) {
                v = *reinterpret_cast<const float4*>(&xr2[i]);
            } else {
                int ia = i + HALF;
                int ib = i + 1 < 0 ? i + 1 + HALF : i + 1;
                float2 a = xr2[ia];
                float2 c = xr2[ib];
                v = make_float4(a.x, a.y, c.x, c.y);
            }
            float2 np = np2[t];
            float p0 = 0.5f * (v.x + v.y) + np.x;
            float p1 = 0.5f * (v.z + v.w) + np.y;
            sp2[t] = make_float2(p0, p1);
            sum   += p0 + p1;
            sumsq += p0 * p0 + p1 * p1;
        }
    } else if ((move & 1) == 0) {
        // Even shift, move%4==2: float2 per pooled element.
        const float2* xr2 = reinterpret_cast<const float2*>(xr);
        const int moff = move >> 1;
        #pragma unroll 4
        for (int t = threadIdx.x; t < HALF_CTA; t += NTHREADS) {
            int j = jbase + t;
            int i = j - moff;
            if (i < 0) i += HALF;
            float2 v = xr2[i];
            float p = 0.5f * (v.x + v.y) + g_npool[j];
            s_pool[t] = p;
            sum += p;
            sumsq += p * p;
        }
    } else {
        // Odd shift: scalar loads with per-element wrap.
        for (int t = threadIdx.x; t < HALF_CTA; t += NTHREADS) {
            int j = jbase + t;
            int i0 = 2 * j - move;
            if (i0 < 0) i0 += L_LEN;
            int i1 = i0 + 1;
            if (i1 >= L_LEN) i1 -= L_LEN;
            float p = 0.5f * (xr[i0] + xr[i1]) + g_npool[j];
            s_pool[t] = p;
            sum += p;
            sumsq += p * p;
        }
    }

    // Local block reduction (16 warps).
    #pragma unroll
    for (int o = 16; o; o >>= 1) {
        sum   += __shfl_down_sync(0xFFFFFFFFu, sum, o);
        sumsq += __shfl_down_sync(0xFFFFFFFFu, sumsq, o);
    }
    const int warp = threadIdx.x >> 5, lane = threadIdx.x & 31;
    if (lane == 0) { rs[warp] = sum; rq[warp] = sumsq; }
    __syncthreads();
    if (warp == 0) {
        float a = (lane < 16) ? rs[lane] : 0.f;
        float q = (lane < 16) ? rq[lane] : 0.f;
        #pragma unroll
        for (int o = 8; o; o >>= 1) {
            a += __shfl_down_sync(0xFFFFFFFFu, a, o);
            q += __shfl_down_sync(0xFFFFFFFFu, q, o);
        }
        if (lane == 0) { s_part[0] = a; s_part[1] = q; }
    }
    __syncthreads();

    // Exchange partial sums with peer CTA via DSMEM.
    asm volatile("barrier.cluster.arrive.aligned;" ::: "memory");
    asm volatile("barrier.cluster.wait.aligned;"   ::: "memory");

    if (threadIdx.x == 0) {
        unsigned int myaddr = smem_u32(&s_part[0]);
        unsigned int peeraddr;
        unsigned int peer = rank ^ 1u;
        asm("mapa.shared::cluster.u32 %0, %1, %2;"
            : "=r"(peeraddr) : "r"(myaddr), "r"(peer));
        float ps, pq;
        asm volatile("ld.shared::cluster.f32 %0, [%1];"     : "=f"(ps) : "r"(peeraddr));
        asm volatile("ld.shared::cluster.f32 %0, [%1 + 4];" : "=f"(pq) : "r"(peeraddr));
        const float inv_n = 1.0f / (float)HALF;
        float a = s_part[0] + ps;
        float q = s_part[1] + pq;
        float mu  = a * inv_n;
        float var = fmaxf(q * inv_n - mu * mu, 0.f);
        s_mu  = mu;
        s_inv = rsqrtf(var);
    }
    __syncthreads();

    // Write phase: LDS.128 (4 pooled) -> two STG.128 {p,p,...}.
    const float mu = s_mu, inv = s_inv;
    const float4* sp4 = reinterpret_cast<const float4*>(s_pool);
    float4* outr4 = reinterpret_cast<float4*>(out + (size_t)b * L_LEN)
                    + (size_t)rank * (2 * QOUT4);
    #pragma unroll 4
    for (int m = threadIdx.x; m < QOUT4; m += NTHREADS) {
        float4 pv = sp4[m];
        float v0 = (pv.x - mu) * inv;
        float v1 = (pv.y - mu) * inv;
        float v2 = (pv.z - mu) * inv;
        float v3 = (pv.w - mu) * inv;
        outr4[2 * m]     = make_float4(v0, v0, v1, v1);
        outr4[2 * m + 1] = make_float4(v2, v2, v3, v3);
    }

    // Peer may still DSMEM-read s_part; hold both CTAs until done.
    asm volatile("barrier.cluster.arrive.aligned;" ::: "memory");
    asm volatile("barrier.cluster.wait.aligned;"   ::: "memory");
}

extern "C" void kernel_launch(void* const* d_in, const int* in_sizes, int n_in,
                              void* d_out, int out_size) {
    const float* x     = (const float*)d_in[0];
    const float* noise = (const float*)d_in[1];
    const int*   move  = (const int*)d_in[2];
    float* out = (float*)d_out;

    cudaFuncSetAttribute(triple_transform_kernel,
                         cudaFuncAttributeMaxDynamicSharedMemorySize,
                         HALF_CTA * (int)sizeof(float));

    noise_pool_kernel<<<(HALF + 255) / 256, 256>>>(noise);
    triple_transform_kernel<<<2 * B_ROWS, NTHREADS, HALF_CTA * sizeof(float)>>>(x, move, out);
}

// round 9
// speedup vs baseline: 1.0177x; 1.0177x over previous
#include <cuda_runtime.h>
#include <cstdint>
#include <math.h>

#define L_LEN     100000
#define B_ROWS    512
#define HALF      50000        // pooled elements per row
#define HALF_CTA  25000        // pooled elements per cluster-rank CTA
#define NPAIRS    12500        // pooled pairs per CTA
#define QOUT4     6250         // float4-quad groups per CTA in write phase
#define NOISE_STD 0.04f
#define NTHREADS  512

// npool[j] = (noise[2j] + noise[2j+1]) * STD / 2. Row-invariant, L2-resident.
// 16B-aligned so float2/float4 reinterpret casts are legal.
__device__ __align__(16) float g_npool[HALF];

__global__ void noise_pool_kernel(const float* __restrict__ noise) {
    int j = blockIdx.x * blockDim.x + threadIdx.x;
    if (j < HALF) {
        float2 n = reinterpret_cast<const float2*>(noise)[j];
        g_npool[j] = (n.x + n.y) * (0.5f * NOISE_STD);
    }
}

__device__ __forceinline__ unsigned int smem_u32(const void* p) {
    unsigned int a;
    asm("{ .reg .u64 t; cvta.to.shared.u64 t, %1; cvt.u32.u64 %0, t; }"
        : "=r"(a) : "l"(p));
    return a;
}

// One row per 2-CTA cluster; 512 threads/CTA, 2 CTAs/SM (100KB smem each).
// Hot loop is a branch-free float4 walk so ptxas front-batches 4 LDG.128.
__global__ __launch_bounds__(NTHREADS, 2) __cluster_dims__(2, 1, 1)
void triple_transform_kernel(const float* __restrict__ x,
                             const int* __restrict__ move_p,
                             float* __restrict__ out) {
    extern __shared__ float s_pool[];              // HALF_CTA floats (100 KB)
    __shared__ float rs[16], rq[16];
    __shared__ float s_part[2];
    __shared__ float s_mu, s_inv;

    unsigned int rank;
    asm("mov.u32 %0, %%cluster_ctarank;" : "=r"(rank));
    const int b = blockIdx.x >> 1;
    const int jbase = (int)rank * HALF_CTA;

    const float* xr = x + (size_t)b * L_LEN;

    int move = *move_p;
    move %= L_LEN; if (move < 0) move += L_LEN;

    float sum = 0.f, sumsq = 0.f;

    if ((move & 3) == 0) {
        // Pair t covers pooled elems (jbase+2t, jbase+2t+1) = one 16B-aligned
        // float4 of x at float2-index i = ibase + 2t (ibase even).
        const float2* xr2 = reinterpret_cast<const float2*>(xr);
        const float2* np2 = reinterpret_cast<const float2*>(g_npool) + rank * NPAIRS;
        float2* sp2 = reinterpret_cast<float2*>(s_pool);
        const int moff  = move >> 1;                // even
        const int ibase = jbase - moff;             // even
        const int W = (ibase < 0) ? ((-ibase) >> 1) : 0;   // wrapped pairs

        // Peeled wrap region (W=25 for move=100): scalar float2 loads.
        for (int t = threadIdx.x; t < W; t += NTHREADS) {
            int i  = ibase + 2 * t;                 // < 0, even
            float2 a = xr2[i + HALF];
            float2 c = xr2[i + 1 + HALF];           // i+1 <= -1, still wraps
            float2 np = np2[t];
            float p0 = 0.5f * (a.x + a.y) + np.x;
            float p1 = 0.5f * (c.x + c.y) + np.y;
            sp2[t] = make_float2(p0, p1);
            sum   += p0 + p1;
            sumsq += p0 * p0 + p1 * p1;
        }

        // Main loop: branch-free, unit-stride float4 array walk.
        const float4* x4 = reinterpret_cast<const float4*>(xr) + (ibase >> 1);
        #pragma unroll 4
        for (int t = W + threadIdx.x; t < NPAIRS; t += NTHREADS) {
            float4 v  = x4[t];                      // LDG.128, batched x4
            float2 np = np2[t];                     // LDG.64 (L2 hit)
            float p0 = 0.5f * (v.x + v.y) + np.x;
            float p1 = 0.5f * (v.z + v.w) + np.y;
            sp2[t] = make_float2(p0, p1);
            sum   += p0 + p1;
            sumsq += p0 * p0 + p1 * p1;
        }
    } else if ((move & 1) == 0) {
        // Even shift, move%4==2: float2 per pooled element (fallback).
        const float2* xr2 = reinterpret_cast<const float2*>(xr);
        const int moff = move >> 1;
        for (int t = threadIdx.x; t < HALF_CTA; t += NTHREADS) {
            int j = jbase + t;
            int i = j - moff;
            if (i < 0) i += HALF;
            float2 v = xr2[i];
            float p = 0.5f * (v.x + v.y) + g_npool[j];
            s_pool[t] = p;
            sum += p;
            sumsq += p * p;
        }
    } else {
        // Odd shift: scalar loads with per-element wrap (fallback).
        for (int t = threadIdx.x; t < HALF_CTA; t += NTHREADS) {
            int j = jbase + t;
            int i0 = 2 * j - move;
            if (i0 < 0) i0 += L_LEN;
            int i1 = i0 + 1;
            if (i1 >= L_LEN) i1 -= L_LEN;
            float p = 0.5f * (xr[i0] + xr[i1]) + g_npool[j];
            s_pool[t] = p;
            sum += p;
            sumsq += p * p;
        }
    }

    // Local block reduction (16 warps).
    #pragma unroll
    for (int o = 16; o; o >>= 1) {
        sum   += __shfl_down_sync(0xFFFFFFFFu, sum, o);
        sumsq += __shfl_down_sync(0xFFFFFFFFu, sumsq, o);
    }
    const int warp = threadIdx.x >> 5, lane = threadIdx.x & 31;
    if (lane == 0) { rs[warp] = sum; rq[warp] = sumsq; }
    __syncthreads();
    if (warp == 0) {
        float a = (lane < 16) ? rs[lane] : 0.f;
        float q = (lane < 16) ? rq[lane] : 0.f;
        #pragma unroll
        for (int o = 8; o; o >>= 1) {
            a += __shfl_down_sync(0xFFFFFFFFu, a, o);
            q += __shfl_down_sync(0xFFFFFFFFu, q, o);
        }
        if (lane == 0) { s_part[0] = a; s_part[1] = q; }
    }
    __syncthreads();

    // Exchange partial sums with peer CTA via DSMEM.
    asm volatile("barrier.cluster.arrive.aligned;" ::: "memory");
    asm volatile("barrier.cluster.wait.aligned;"   ::: "memory");

    if (threadIdx.x == 0) {
        unsigned int myaddr = smem_u32(&s_part[0]);
        unsigned int peeraddr;
        unsigned int peer = rank ^ 1u;
        asm("mapa.shared::cluster.u32 %0, %1, %2;"
            : "=r"(peeraddr) : "r"(myaddr), "r"(peer));
        float ps, pq;
        asm volatile("ld.shared::cluster.f32 %0, [%1];"     : "=f"(ps) : "r"(peeraddr));
        asm volatile("ld.shared::cluster.f32 %0, [%1 + 4];" : "=f"(pq) : "r"(peeraddr));
        const float inv_n = 1.0f / (float)HALF;
        float a = s_part[0] + ps;
        float q = s_part[1] + pq;
        float mu  = a * inv_n;
        float var = fmaxf(q * inv_n - mu * mu, 0.f);
        s_mu  = mu;
        s_inv = rsqrtf(var);
    }
    __syncthreads();

    // Write phase: LDS.128 (4 pooled) -> two STG.128 {p,p,...}. Branch-free.
    const float mu = s_mu, inv = s_inv;
    const float4* sp4 = reinterpret_cast<const float4*>(s_pool);
    float4* outr4 = reinterpret_cast<float4*>(out + (size_t)b * L_LEN)
                    + (size_t)rank * (2 * QOUT4);
    #pragma unroll 4
    for (int m = threadIdx.x; m < QOUT4; m += NTHREADS) {
        float4 pv = sp4[m];
        float v0 = (pv.x - mu) * inv;
        float v1 = (pv.y - mu) * inv;
        float v2 = (pv.z - mu) * inv;
        float v3 = (pv.w - mu) * inv;
        outr4[2 * m]     = make_float4(v0, v0, v1, v1);
        outr4[2 * m + 1] = make_float4(v2, v2, v3, v3);
    }

    // Peer may still DSMEM-read s_part; hold both CTAs until done.
    asm volatile("barrier.cluster.arrive.aligned;" ::: "memory");
    asm volatile("barrier.cluster.wait.aligned;"   ::: "memory");
}

extern "C" void kernel_launch(void* const* d_in, const int* in_sizes, int n_in,
                              void* d_out, int out_size) {
    const float* x     = (const float*)d_in[0];
    const float* noise = (const float*)d_in[1];
    const int*   move  = (const int*)d_in[2];
    float* out = (float*)d_out;

    cudaFuncSetAttribute(triple_transform_kernel,
                         cudaFuncAttributeMaxDynamicSharedMemorySize,
                         HALF_CTA * (int)sizeof(float));

    noise_pool_kernel<<<(HALF + 255) / 256, 256>>>(noise);
    triple_transform_kernel<<<2 * B_ROWS, NTHREADS, HALF_CTA * sizeof(float)>>>(x, move, out);
}

// round 11
// speedup vs baseline: 1.0389x; 1.0208x over previous
#include <cuda_runtime.h>
#include <cstdint>
#include <math.h>

#define L_LEN     100000
#define B_ROWS    512
#define HALF      50000        // pooled elements per row
#define HALF_CTA  25000        // pooled elements per cluster-rank CTA
#define NPAIRS    12500        // pooled pairs (float4 x-loads) per CTA
#define QOUT4     6250         // float4 groups of pooled per CTA (write phase)
#define NOISE_STD 0.04f
#define NTHREADS  1024

// npool[j] = (noise[2j] + noise[2j+1]) * STD / 2. Row-invariant, L2-resident.
__device__ __align__(16) float g_npool[HALF];

__global__ void noise_pool_kernel(const float* __restrict__ noise) {
    int j = blockIdx.x * blockDim.x + threadIdx.x;
    if (j < HALF) {
        float2 n = reinterpret_cast<const float2*>(noise)[j];
        g_npool[j] = (n.x + n.y) * (0.5f * NOISE_STD);
    }
}

__device__ __forceinline__ unsigned int smem_u32(const void* p) {
    unsigned int a;
    asm("{ .reg .u64 t; cvta.to.shared.u64 t, %1; cvt.u32.u64 %0, t; }"
        : "=r"(a) : "l"(p));
    return a;
}

// One row per 2-CTA cluster; 1024 threads/CTA, 2 CTAs/SM (100KB smem each,
// 64 warps/SM). Load loop hand-pairs two independent LDG.128 per iteration so
// >=64KB/SM of x-bytes are in flight regardless of ptxas unrolling choices.
__global__ __launch_bounds__(NTHREADS, 2) __cluster_dims__(2, 1, 1)
void triple_transform_kernel(const float* __restrict__ x,
                             const int* __restrict__ move_p,
                             float* __restrict__ out) {
    extern __shared__ float s_pool[];              // HALF_CTA floats (100 KB)
    __shared__ float rs[32], rq[32];
    __shared__ float s_part[2];
    __shared__ float s_mu, s_inv;

    unsigned int rank;
    asm("mov.u32 %0, %%cluster_ctarank;" : "=r"(rank));
    const int b = blockIdx.x >> 1;
    const int jbase = (int)rank * HALF_CTA;

    const float* xr = x + (size_t)b * L_LEN;

    int move = *move_p;
    move %= L_LEN; if (move < 0) move += L_LEN;

    float sum = 0.f, sumsq = 0.f;

    if ((move & 3) == 0) {
        // Pair t covers pooled elems (jbase+2t, jbase+2t+1) = one 16B-aligned
        // float4 of x at float2-index ibase + 2t (ibase even).
        const float2* xr2 = reinterpret_cast<const float2*>(xr);
        const float2* np2 = reinterpret_cast<const float2*>(g_npool) + rank * NPAIRS;
        float2* sp2 = reinterpret_cast<float2*>(s_pool);
        const int moff  = move >> 1;                // even
        const int ibase = jbase - moff;             // even
        const int W = (ibase < 0) ? ((-ibase) >> 1) : 0;   // wrapped pairs

        // Peeled wrap region (W=25 for move=100): scalar float2 loads.
        for (int t = threadIdx.x; t < W; t += NTHREADS) {
            int i  = ibase + 2 * t;                 // < 0, even
            float2 a = xr2[i + HALF];
            float2 c = xr2[i + 1 + HALF];
            float2 np = np2[t];
            float p0 = 0.5f * (a.x + a.y) + np.x;
            float p1 = 0.5f * (c.x + c.y) + np.y;
            sp2[t] = make_float2(p0, p1);
            sum   += p0 + p1;
            sumsq += p0 * p0 + p1 * p1;
        }

        // Main loop: two independent LDG.128 + two LDG.64 issued before any
        // consumer in every iteration (guaranteed batching, branch-free).
        const float4* x4 = reinterpret_cast<const float4*>(xr) + (ibase >> 1);
        int t = W + threadIdx.x;
        for (; t + NTHREADS < NPAIRS; t += 2 * NTHREADS) {
            float4 va = x4[t];
            float4 vb = x4[t + NTHREADS];
            float2 na = np2[t];
            float2 nb = np2[t + NTHREADS];
            float pa0 = 0.5f * (va.x + va.y) + na.x;
            float pa1 = 0.5f * (va.z + va.w) + na.y;
            float pb0 = 0.5f * (vb.x + vb.y) + nb.x;
            float pb1 = 0.5f * (vb.z + vb.w) + nb.y;
            sp2[t]            = make_float2(pa0, pa1);
            sp2[t + NTHREADS] = make_float2(pb0, pb1);
            sum   += (pa0 + pa1) + (pb0 + pb1);
            sumsq += (pa0 * pa0 + pa1 * pa1) + (pb0 * pb0 + pb1 * pb1);
        }
        for (; t < NPAIRS; t += NTHREADS) {
            float4 v  = x4[t];
            float2 np = np2[t];
            float p0 = 0.5f * (v.x + v.y) + np.x;
            float p1 = 0.5f * (v.z + v.w) + np.y;
            sp2[t] = make_float2(p0, p1);
            sum   += p0 + p1;
            sumsq += p0 * p0 + p1 * p1;
        }
    } else if ((move & 1) == 0) {
        // Even shift, move%4==2: float2 per pooled element (fallback).
        const float2* xr2 = reinterpret_cast<const float2*>(xr);
        const int moff = move >> 1;
        for (int t = threadIdx.x; t < HALF_CTA; t += NTHREADS) {
            int j = jbase + t;
            int i = j - moff;
            if (i < 0) i += HALF;
            float2 v = xr2[i];
            float p = 0.5f * (v.x + v.y) + g_npool[j];
            s_pool[t] = p;
            sum += p;
            sumsq += p * p;
        }
    } else {
        // Odd shift: scalar loads with per-element wrap (fallback).
        for (int t = threadIdx.x; t < HALF_CTA; t += NTHREADS) {
            int j = jbase + t;
            int i0 = 2 * j - move;
            if (i0 < 0) i0 += L_LEN;
            int i1 = i0 + 1;
            if (i1 >= L_LEN) i1 -= L_LEN;
            float p = 0.5f * (xr[i0] + xr[i1]) + g_npool[j];
            s_pool[t] = p;
            sum += p;
            sumsq += p * p;
        }
    }

    // Local block reduction (32 warps).
    #pragma unroll
    for (int o = 16; o; o >>= 1) {
        sum   += __shfl_down_sync(0xFFFFFFFFu, sum, o);
        sumsq += __shfl_down_sync(0xFFFFFFFFu, sumsq, o);
    }
    const int warp = threadIdx.x >> 5, lane = threadIdx.x & 31;
    if (lane == 0) { rs[warp] = sum; rq[warp] = sumsq; }
    __syncthreads();
    if (warp == 0) {
        float a = rs[lane], q = rq[lane];
        #pragma unroll
        for (int o = 16; o; o >>= 1) {
            a += __shfl_down_sync(0xFFFFFFFFu, a, o);
            q += __shfl_down_sync(0xFFFFFFFFu, q, o);
        }
        if (lane == 0) { s_part[0] = a; s_part[1] = q; }
    }
    __syncthreads();

    // Exchange partial sums with peer CTA via DSMEM.
    asm volatile("barrier.cluster.arrive.aligned;" ::: "memory");
    asm volatile("barrier.cluster.wait.aligned;"   ::: "memory");

    if (threadIdx.x == 0) {
        unsigned int myaddr = smem_u32(&s_part[0]);
        unsigned int peeraddr;
        unsigned int peer = rank ^ 1u;
        asm("mapa.shared::cluster.u32 %0, %1, %2;"
            : "=r"(peeraddr) : "r"(myaddr), "r"(peer));
        float ps, pq;
        asm volatile("ld.shared::cluster.f32 %0, [%1];"     : "=f"(ps) : "r"(peeraddr));
        asm volatile("ld.shared::cluster.f32 %0, [%1 + 4];" : "=f"(pq) : "r"(peeraddr));
        const float inv_n = 1.0f / (float)HALF;
        float a = s_part[0] + ps;
        float q = s_part[1] + pq;
        float mu  = a * inv_n;
        float var = fmaxf(q * inv_n - mu * mu, 0.f);
        s_mu  = mu;
        s_inv = rsqrtf(var);
    }
    __syncthreads();

    // Write phase: LDS.128 (4 pooled) -> two STG.128 {p,p,...}.
    const float mu = s_mu, inv = s_inv;
    const float4* sp4 = reinterpret_cast<const float4*>(s_pool);
    float4* outr4 = reinterpret_cast<float4*>(out + (size_t)b * L_LEN)
                    + (size_t)rank * (2 * QOUT4);
    for (int m = threadIdx.x; m < QOUT4; m += NTHREADS) {
        float4 pv = sp4[m];
        float v0 = (pv.x - mu) * inv;
        float v1 = (pv.y - mu) * inv;
        float v2 = (pv.z - mu) * inv;
        float v3 = (pv.w - mu) * inv;
        outr4[2 * m]     = make_float4(v0, v0, v1, v1);
        outr4[2 * m + 1] = make_float4(v2, v2, v3, v3);
    }

    // Peer may still DSMEM-read s_part; hold both CTAs until done.
    asm volatile("barrier.cluster.arrive.aligned;" ::: "memory");
    asm volatile("barrier.cluster.wait.aligned;"   ::: "memory");
}

extern "C" void kernel_launch(void* const* d_in, const int* in_sizes, int n_in,
                              void* d_out, int out_size) {
    const float* x     = (const float*)d_in[0];
    const float* noise = (const float*)d_in[1];
    const int*   move  = (const int*)d_in[2];
    float* out = (float*)d_out;

    cudaFuncSetAttribute(triple_transform_kernel,
                         cudaFuncAttributeMaxDynamicSharedMemorySize,
                         HALF_CTA * (int)sizeof(float));

    noise_pool_kernel<<<(HALF + 255) / 256, 256>>>(noise);
    triple_transform_kernel<<<2 * B_ROWS, NTHREADS, HALF_CTA * sizeof(float)>>>(x, move, out);
}